// round 8
// baseline (speedup 1.0000x reference)
#include <cuda_runtime.h>
#include <math.h>

// Problem constants (fixed by setup_inputs)
#define Bq    2
#define Cq    64
#define Gq    8
#define NBq   9
#define Hq    256
#define Wq    320
#define HWq   (Hq * Wq)              // 81920
#define NCELL (Bq * Hq * Wq)         // 163840
#define NPOS  (Bq * NBq * Hq * Wq)   // 1474560
#define EPSq  1e-5

// ---------------- scratch (static device allocations are the sanctioned path) ----
__device__ float  g_ref_t[Bq * Hq * Wq * Cq];   // [B,H,W,C] transposed image (~42MB)
__device__ float  g_v[NPOS * Gq];               // per-position 8-dim correlation (~47MB)
__device__ double g_st0[32];                    // sum / sumsq of y0 (16 ch)
__device__ double g_st1[16];                    // sum / sumsq of y1 (8 ch)
__device__ float  g_sc0[16], g_sh0[16];         // folded BN0 scale/shift
__device__ float  g_sc1[8],  g_sh1[8];          // folded BN1 scale/shift

// ---------------- K0: zero the stats accumulators (graph-replay determinism) ----
__global__ void k_zero() {
    int t = threadIdx.x;
    if (t < 32) g_st0[t] = 0.0;
    if (t < 16) g_st1[t] = 0.0;
}

// ---------------- K1: transpose [B,C,H,W] -> [B,H,W,C] -------------------------
// grid (W/32, C/32, B*H), block (32,8). 32x33 shared tile, both sides coalesced.
__global__ void k_transpose(const float* __restrict__ in) {
    __shared__ float tile[32][33];
    int bh = blockIdx.z;                  // b*H + h
    int c0 = blockIdx.y << 5;
    int w0 = blockIdx.x << 5;
    int b  = bh >> 8;                     // H = 256
    int h  = bh & 255;
    const float* src = in + (size_t)b * Cq * HWq + (size_t)h * Wq;
    int tx = threadIdx.x, ty = threadIdx.y;
#pragma unroll
    for (int r = 0; r < 4; r++)
        tile[ty + r * 8][tx] = src[(size_t)(c0 + ty + r * 8) * HWq + (w0 + tx)];
    __syncthreads();
    float* dst = g_ref_t + (size_t)bh * Wq * Cq;
#pragma unroll
    for (int r = 0; r < 4; r++)
        dst[(size_t)(w0 + ty + r * 8) * Cq + (c0 + tx)] = tile[tx][ty + r * 8];
}

// ---------------- K2: bilinear gather + per-group correlation -> g_v -----------
// 8 threads per (b,h,w) cell; thread j owns channel group j (channels j*8..j*8+7,
// contiguous in g_ref_t). Each group loops over all 9 neighbors so the center
// vector is read once. Corner reads are two float4s per thread = contiguous
// fully-utilized 256B per corner per position.
__global__ void __launch_bounds__(256) k_gather(const float* __restrict__ grd) {
    int t    = blockIdx.x * 256 + threadIdx.x;
    int cell = t >> 3;
    int j    = t & 7;
    int w  = cell % Wq;
    int hh = cell / Wq;
    int h  = hh & (Hq - 1);
    int b  = hh >> 8;

    const float4* cen = (const float4*)(g_ref_t + cell * Cq + j * 8);
    float4 r0 = cen[0], r1 = cen[1];

    const float* base = g_ref_t + b * HWq * Cq + j * 8;
    int posb = (b * NBq * Hq + h) * Wq + w;

#pragma unroll 1
    for (int n = 0; n < NBq; n++) {
        int pos = posb + n * HWq;
        float2 gxy = ((const float2*)grd)[pos];
        // matches: clip(((g+1)*S - 1)*0.5, 0, S-1)
        float ix = fminf(fmaxf(((gxy.x + 1.0f) * (float)Wq - 1.0f) * 0.5f, 0.0f), (float)(Wq - 1));
        float iy = fminf(fmaxf(((gxy.y + 1.0f) * (float)Hq - 1.0f) * 0.5f, 0.0f), (float)(Hq - 1));
        float fx = floorf(ix), fy = floorf(iy);
        float ax = ix - fx,    ay = iy - fy;
        int x0 = (int)fx,      y0 = (int)fy;
        int x1 = min(x0 + 1, Wq - 1), y1 = min(y0 + 1, Hq - 1);
        float w00 = (1.0f - ax) * (1.0f - ay);
        float w01 = ax * (1.0f - ay);
        float w10 = (1.0f - ax) * ay;
        float w11 = ax * ay;

        const float4* pA = (const float4*)(base + (y0 * Wq + x0) * Cq);
        const float4* pB = (const float4*)(base + (y0 * Wq + x1) * Cq);
        const float4* pC = (const float4*)(base + (y1 * Wq + x0) * Cq);
        const float4* pD = (const float4*)(base + (y1 * Wq + x1) * Cq);
        float4 A0 = pA[0], A1 = pA[1];
        float4 B0 = pB[0], B1 = pB[1];
        float4 C0 = pC[0], C1 = pC[1];
        float4 D0 = pD[0], D1 = pD[1];

        float acc, s;
        s = w00*A0.x + w01*B0.x + w10*C0.x + w11*D0.x; acc  = s * r0.x;
        s = w00*A0.y + w01*B0.y + w10*C0.y + w11*D0.y; acc += s * r0.y;
        s = w00*A0.z + w01*B0.z + w10*C0.z + w11*D0.z; acc += s * r0.z;
        s = w00*A0.w + w01*B0.w + w10*C0.w + w11*D0.w; acc += s * r0.w;
        s = w00*A1.x + w01*B1.x + w10*C1.x + w11*D1.x; acc += s * r1.x;
        s = w00*A1.y + w01*B1.y + w10*C1.y + w11*D1.y; acc += s * r1.y;
        s = w00*A1.z + w01*B1.z + w10*C1.z + w11*D1.z; acc += s * r1.z;
        s = w00*A1.w + w01*B1.w + w10*C1.w + w11*D1.w; acc += s * r1.w;

        g_v[pos * 8 + j] = acc * 0.125f;   // mean over C/G = 8 (exact /8)
    }
}

// helper: warp+block reduce a per-thread value into shared slot, then one
// double atomic per block per slot (keeps global atomic count ~30K total).
__device__ __forceinline__ void block_acc(float val, float* slot) {
#pragma unroll
    for (int off = 16; off; off >>= 1)
        val += __shfl_down_sync(0xffffffffu, val, off);
    if ((threadIdx.x & 31) == 0) atomicAdd(slot, val);
}

// ---------------- K3: sum / sumsq of y0 = w0 @ v --------------------------------
__global__ void __launch_bounds__(256) k_stats0(const float* __restrict__ w0) {
    __shared__ float sw[128];
    __shared__ float red[32];
    if (threadIdx.x < 128) sw[threadIdx.x] = w0[threadIdx.x];
    if (threadIdx.x < 32)  red[threadIdx.x] = 0.0f;
    __syncthreads();

    float s[16], q[16];
#pragma unroll
    for (int o = 0; o < 16; o++) { s[o] = 0.0f; q[o] = 0.0f; }

    for (int pos = blockIdx.x * 256 + threadIdx.x; pos < NPOS; pos += gridDim.x * 256) {
        const float4* pv = (const float4*)(g_v + pos * 8);
        float4 v0 = pv[0], v1 = pv[1];
        float v[8] = {v0.x, v0.y, v0.z, v0.w, v1.x, v1.y, v1.z, v1.w};
#pragma unroll
        for (int o = 0; o < 16; o++) {
            float y = 0.0f;
#pragma unroll
            for (int i = 0; i < 8; i++) y = fmaf(sw[o * 8 + i], v[i], y);
            s[o] += y;
            q[o]  = fmaf(y, y, q[o]);
        }
    }
#pragma unroll
    for (int o = 0; o < 16; o++) { block_acc(s[o], &red[o]); block_acc(q[o], &red[16 + o]); }
    __syncthreads();
    if (threadIdx.x < 32) atomicAdd(&g_st0[threadIdx.x], (double)red[threadIdx.x]);
}

// ---------------- K4: fold BN0 + gamma/beta into scale/shift --------------------
__global__ void k_fin0(const float* __restrict__ g0, const float* __restrict__ b0) {
    int o = threadIdx.x;
    if (o >= 16) return;
    double N    = (double)NPOS;
    double m    = g_st0[o] / N;
    double var  = g_st0[16 + o] / N - m * m;
    double rstd = rsqrt(var + EPSq);
    g_sc0[o] = (float)((double)g0[o] * rstd);
    g_sh0[o] = (float)((double)b0[o] - m * rstd * (double)g0[o]);
}

// ---------------- K5: sum / sumsq of y1 = w1 @ relu(bn0(y0)) --------------------
__global__ void __launch_bounds__(256) k_stats1(const float* __restrict__ w0,
                                                const float* __restrict__ w1) {
    __shared__ float sw0[128], sw1[128], sc[16], sh[16];
    __shared__ float red[16];
    if (threadIdx.x < 128) { sw0[threadIdx.x] = w0[threadIdx.x]; sw1[threadIdx.x] = w1[threadIdx.x]; }
    if (threadIdx.x < 16)  { sc[threadIdx.x] = g_sc0[threadIdx.x]; sh[threadIdx.x] = g_sh0[threadIdx.x]; red[threadIdx.x] = 0.0f; }
    __syncthreads();

    float s[8], q[8];
#pragma unroll
    for (int o = 0; o < 8; o++) { s[o] = 0.0f; q[o] = 0.0f; }

    for (int pos = blockIdx.x * 256 + threadIdx.x; pos < NPOS; pos += gridDim.x * 256) {
        const float4* pv = (const float4*)(g_v + pos * 8);
        float4 v0 = pv[0], v1 = pv[1];
        float v[8] = {v0.x, v0.y, v0.z, v0.w, v1.x, v1.y, v1.z, v1.w};
        float z[16];
#pragma unroll
        for (int o = 0; o < 16; o++) {
            float y = 0.0f;
#pragma unroll
            for (int i = 0; i < 8; i++) y = fmaf(sw0[o * 8 + i], v[i], y);
            z[o] = fmaxf(fmaf(y, sc[o], sh[o]), 0.0f);
        }
#pragma unroll
        for (int o = 0; o < 8; o++) {
            float y = 0.0f;
#pragma unroll
            for (int i = 0; i < 16; i++) y = fmaf(sw1[o * 16 + i], z[i], y);
            s[o] += y;
            q[o]  = fmaf(y, y, q[o]);
        }
    }
#pragma unroll
    for (int o = 0; o < 8; o++) { block_acc(s[o], &red[o]); block_acc(q[o], &red[8 + o]); }
    __syncthreads();
    if (threadIdx.x < 16) atomicAdd(&g_st1[threadIdx.x], (double)red[threadIdx.x]);
}

// ---------------- K6: fold BN1 --------------------------------------------------
__global__ void k_fin1(const float* __restrict__ g1, const float* __restrict__ b1) {
    int o = threadIdx.x;
    if (o >= 8) return;
    double N    = (double)NPOS;
    double m    = g_st1[o] / N;
    double var  = g_st1[8 + o] / N - m * m;
    double rstd = rsqrt(var + EPSq);
    g_sc1[o] = (float)((double)g1[o] * rstd);
    g_sh1[o] = (float)((double)b1[o] - m * rstd * (double)g1[o]);
}

// ---------------- K7: final MLP + sigmoid ---------------------------------------
__global__ void __launch_bounds__(256) k_final(const float* __restrict__ w0,
                                               const float* __restrict__ w1,
                                               const float* __restrict__ ws,
                                               const float* __restrict__ bs,
                                               float* __restrict__ out) {
    __shared__ float sw0[128], sw1[128], sc0[16], sh0[16], sc1[8], sh1[8], sws[8];
    __shared__ float sbs;
    if (threadIdx.x < 128) { sw0[threadIdx.x] = w0[threadIdx.x]; sw1[threadIdx.x] = w1[threadIdx.x]; }
    if (threadIdx.x < 16)  { sc0[threadIdx.x] = g_sc0[threadIdx.x]; sh0[threadIdx.x] = g_sh0[threadIdx.x]; }
    if (threadIdx.x < 8)   { sc1[threadIdx.x] = g_sc1[threadIdx.x]; sh1[threadIdx.x] = g_sh1[threadIdx.x]; sws[threadIdx.x] = ws[threadIdx.x]; }
    if (threadIdx.x == 0)  sbs = bs[0];
    __syncthreads();

    int pos = blockIdx.x * 256 + threadIdx.x;
    if (pos >= NPOS) return;

    const float4* pv = (const float4*)(g_v + pos * 8);
    float4 v0 = pv[0], v1 = pv[1];
    float v[8] = {v0.x, v0.y, v0.z, v0.w, v1.x, v1.y, v1.z, v1.w};

    float z[16];
#pragma unroll
    for (int o = 0; o < 16; o++) {
        float y = 0.0f;
#pragma unroll
        for (int i = 0; i < 8; i++) y = fmaf(sw0[o * 8 + i], v[i], y);
        z[o] = fmaxf(fmaf(y, sc0[o], sh0[o]), 0.0f);
    }
    float z1[8];
#pragma unroll
    for (int o = 0; o < 8; o++) {
        float y = 0.0f;
#pragma unroll
        for (int i = 0; i < 16; i++) y = fmaf(sw1[o * 16 + i], z[i], y);
        z1[o] = fmaxf(fmaf(y, sc1[o], sh1[o]), 0.0f);
    }
    float acc = sbs;
#pragma unroll
    for (int i = 0; i < 8; i++) acc = fmaf(sws[i], z1[i], acc);

    out[pos] = 1.0f / (1.0f + expf(-acc));
}

// ---------------- launch --------------------------------------------------------
extern "C" void kernel_launch(void* const* d_in, const int* in_sizes, int n_in,
                              void* d_out, int out_size) {
    const float* ref  = (const float*)d_in[0];
    const float* grid = (const float*)d_in[1];
    const float* w0   = (const float*)d_in[2];
    const float* g0   = (const float*)d_in[3];
    const float* b0   = (const float*)d_in[4];
    const float* w1   = (const float*)d_in[5];
    const float* g1   = (const float*)d_in[6];
    const float* b1   = (const float*)d_in[7];
    const float* ws   = (const float*)d_in[8];
    const float* bs   = (const float*)d_in[9];
    float* out = (float*)d_out;

    k_zero<<<1, 32>>>();
    k_transpose<<<dim3(Wq / 32, Cq / 32, Bq * Hq), dim3(32, 8)>>>(ref);
    k_gather<<<(NCELL * 8) / 256, 256>>>(grid);          // 5120 blocks, exact
    k_stats0<<<1184, 256>>>(w0);
    k_fin0<<<1, 16>>>(g0, b0);
    k_stats1<<<1184, 256>>>(w0, w1);
    k_fin1<<<1, 8>>>(g1, b1);
    k_final<<<NPOS / 256, 256>>>(w0, w1, ws, bs, out);   // 5760 blocks, exact
}

// round 9
// speedup vs baseline: 3.4727x; 3.4727x over previous
#include <cuda_runtime.h>
#include <cuda_fp16.h>
#include <math.h>

// Problem constants (fixed by setup_inputs)
#define Bq    2
#define Cq    64
#define NBq   9
#define Hq    256
#define Wq    320
#define HWq   (Hq * Wq)              // 81920
#define NCELL (Bq * Hq * Wq)         // 163840
#define NPOS  (Bq * NBq * Hq * Wq)   // 1474560
#define EPSq  1e-5

// ---------------- scratch ------------------------------------------------------
__device__ __align__(16) __half g_ref_t[(size_t)NCELL * Cq];  // [B,H,W,C] fp16 (~21MB)
__device__ __align__(16) float  g_v[(size_t)NPOS * 8];        // correlation vecs (~47MB)
__device__ double g_mom[72];          // [0..63] sum v_i*v_j, [64..71] sum v_i
__device__ double g_st1[16];          // sum / sumsq of y1 (8 ch)
__device__ __align__(16) float g_sc0[16], g_sh0[16];
__device__ __align__(16) float g_sc1[8],  g_sh1[8];

__constant__ float c_w0[128];
__constant__ float c_w1[128];
__constant__ float c_ws[8];
__constant__ float c_bs[1];

// ---------------- K0: zero accumulators (graph-replay determinism) --------------
__global__ void k_zero() {
    int t = threadIdx.x;
    if (t < 72) g_mom[t] = 0.0;
    if (t < 16) g_st1[t] = 0.0;
}

// ---------------- K1: transpose [B,C,H,W] fp32 -> [B,H,W,C] fp16 ----------------
// grid (W/32, 1, B*H), block (32,16). Handles all 64 channels per tile so the
// half2 stores are 128B fully coalesced.
__global__ void k_transpose(const float* __restrict__ in) {
    __shared__ float tile[64][33];
    int bh = blockIdx.z;                 // b*H + h
    int w0 = blockIdx.x << 5;
    int b  = bh >> 8;                    // H = 256
    int h  = bh & 255;
    const float* src = in + (size_t)b * Cq * HWq + (size_t)h * Wq + w0;
    int tx = threadIdx.x, ty = threadIdx.y;
#pragma unroll
    for (int r = 0; r < 4; r++)
        tile[ty + r * 16][tx] = src[(size_t)(ty + r * 16) * HWq + tx];
    __syncthreads();
    __half2* dst = (__half2*)(g_ref_t + (size_t)bh * Wq * Cq) + (size_t)w0 * 32;
#pragma unroll
    for (int r = 0; r < 2; r++) {
        int wl = ty + r * 16;
        dst[(size_t)wl * 32 + tx] =
            __floats2half2_rn(tile[2 * tx][wl], tile[2 * tx + 1][wl]);
    }
}

// ---------------- K2: bilinear gather + correlation + BN0 moments ---------------
// 8 threads per (b,h,w) cell; thread j owns channels j*8..j*8+7 (16B = uint4 in
// fp16). Loops over the 9 neighbors so the center vector is read once. Also
// accumulates sum(v_i) and sum(v_i*v_j) for the BN0 closed-form stats.
#define BLEND2(comp, ck)                                                         \
    {                                                                            \
        float2 fa = __half22float2(*(const __half2*)&Au.comp);                   \
        float2 fb = __half22float2(*(const __half2*)&Bu.comp);                   \
        float2 fc = __half22float2(*(const __half2*)&Cu.comp);                   \
        float2 fd = __half22float2(*(const __half2*)&Du.comp);                   \
        float s0 = fmaf(w11, fd.x, fmaf(w10, fc.x, fmaf(w01, fb.x, w00 * fa.x)));\
        float s1 = fmaf(w11, fd.y, fmaf(w10, fc.y, fmaf(w01, fb.y, w00 * fa.y)));\
        acc = fmaf(s0, cf[ck], acc);                                             \
        acc = fmaf(s1, cf[ck + 1], acc);                                         \
    }

__global__ void __launch_bounds__(256, 4) k_gather(const float* __restrict__ grd) {
    __shared__ float sred[72];
    int t    = blockIdx.x * 256 + threadIdx.x;
    int cell = t >> 3;
    int j    = t & 7;
    int w  = cell % Wq;
    int hh = cell / Wq;
    int h  = hh & (Hq - 1);
    int b  = hh >> 8;

    const uint4* refu = (const uint4*)g_ref_t;    // 8 halves per uint4
    uint4 cu = refu[(size_t)cell * 8 + j];
    float cf[8];
    {
        float2 f;
        f = __half22float2(*(const __half2*)&cu.x); cf[0] = f.x; cf[1] = f.y;
        f = __half22float2(*(const __half2*)&cu.y); cf[2] = f.x; cf[3] = f.y;
        f = __half22float2(*(const __half2*)&cu.z); cf[4] = f.x; cf[5] = f.y;
        f = __half22float2(*(const __half2*)&cu.w); cf[6] = f.x; cf[7] = f.y;
    }

    const uint4* base = refu + (size_t)b * HWq * 8;
    int posb = (b * NBq * Hq + h) * Wq + w;

    float M[8];
#pragma unroll
    for (int i = 0; i < 8; i++) M[i] = 0.0f;
    float Sv = 0.0f;

#pragma unroll 1
    for (int n = 0; n < NBq; n++) {
        int pos = posb + n * HWq;
        float2 g = ((const float2*)grd)[pos];
        float ix = fminf(fmaxf(((g.x + 1.0f) * (float)Wq - 1.0f) * 0.5f, 0.0f), (float)(Wq - 1));
        float iy = fminf(fmaxf(((g.y + 1.0f) * (float)Hq - 1.0f) * 0.5f, 0.0f), (float)(Hq - 1));
        float fx = floorf(ix), fy = floorf(iy);
        float ax = ix - fx,    ay = iy - fy;
        int x0 = (int)fx,      y0 = (int)fy;
        int x1 = min(x0 + 1, Wq - 1), y1 = min(y0 + 1, Hq - 1);
        float w00 = (1.0f - ax) * (1.0f - ay);
        float w01 = ax * (1.0f - ay);
        float w10 = (1.0f - ax) * ay;
        float w11 = ax * ay;

        uint4 Au = base[(size_t)(y0 * Wq + x0) * 8 + j];
        uint4 Bu = base[(size_t)(y0 * Wq + x1) * 8 + j];
        uint4 Cu = base[(size_t)(y1 * Wq + x0) * 8 + j];
        uint4 Du = base[(size_t)(y1 * Wq + x1) * 8 + j];

        float acc = 0.0f;
        BLEND2(x, 0) BLEND2(y, 2) BLEND2(z, 4) BLEND2(w, 6)

        float v = acc * 0.125f;            // mean over C/G = 8 (exact)
        g_v[(size_t)pos * 8 + j] = v;

        Sv += v;
#pragma unroll
        for (int i = 0; i < 8; i++) {
            float vi = __shfl_sync(0xffffffffu, v, i, 8);
            M[i] = fmaf(vi, v, M[i]);
        }
    }

    // reduce across the 4 groups in the warp (lanes j, j+8, j+16, j+24)
#pragma unroll
    for (int i = 0; i < 8; i++) {
        M[i] += __shfl_down_sync(0xffffffffu, M[i], 16);
        M[i] += __shfl_down_sync(0xffffffffu, M[i], 8);
    }
    Sv += __shfl_down_sync(0xffffffffu, Sv, 16);
    Sv += __shfl_down_sync(0xffffffffu, Sv, 8);

    if (threadIdx.x < 72) sred[threadIdx.x] = 0.0f;
    __syncthreads();
    if ((threadIdx.x & 31) < 8) {
#pragma unroll
        for (int i = 0; i < 8; i++) atomicAdd(&sred[i * 8 + j], M[i]);
        atomicAdd(&sred[64 + j], Sv);
    }
    __syncthreads();
    if (threadIdx.x < 72) atomicAdd(&g_mom[threadIdx.x], (double)sred[threadIdx.x]);
}

// ---------------- K3: BN0 stats from moments, fold into scale/shift -------------
__global__ void k_fin0(const float* __restrict__ g0, const float* __restrict__ b0) {
    int o = threadIdx.x;
    if (o >= 16) return;
    const double N = (double)NPOS;
    double m = 0.0, e2 = 0.0;
#pragma unroll
    for (int i = 0; i < 8; i++) {
        double wi = (double)c_w0[o * 8 + i];
        m += wi * g_mom[64 + i];
#pragma unroll
        for (int k = 0; k < 8; k++)
            e2 += wi * (double)c_w0[o * 8 + k] * g_mom[i * 8 + k];
    }
    m /= N; e2 /= N;
    double rstd = rsqrt(e2 - m * m + EPSq);
    double gg = (double)g0[o];
    g_sc0[o] = (float)(gg * rstd);
    g_sh0[o] = (float)((double)b0[o] - m * rstd * gg);
}

// helper: warp-reduce then one shared atomic per warp
__device__ __forceinline__ void block_acc(float val, float* slot) {
#pragma unroll
    for (int off = 16; off; off >>= 1)
        val += __shfl_down_sync(0xffffffffu, val, off);
    if ((threadIdx.x & 31) == 0) atomicAdd(slot, val);
}

// ---------------- K4: sum / sumsq of y1 = w1 @ relu(bn0(w0 @ v)) ----------------
__global__ void __launch_bounds__(256, 3) k_stats1() {
    __shared__ float red[16];
    if (threadIdx.x < 16) red[threadIdx.x] = 0.0f;
    __syncthreads();

    float sc0[16], sh0[16];
    {
        const float4* p = (const float4*)g_sc0;
        float4 a0 = p[0], a1 = p[1], a2 = p[2], a3 = p[3];
        float t0[16] = {a0.x,a0.y,a0.z,a0.w, a1.x,a1.y,a1.z,a1.w,
                        a2.x,a2.y,a2.z,a2.w, a3.x,a3.y,a3.z,a3.w};
        const float4* q = (const float4*)g_sh0;
        float4 b0v = q[0], b1v = q[1], b2v = q[2], b3v = q[3];
        float t1[16] = {b0v.x,b0v.y,b0v.z,b0v.w, b1v.x,b1v.y,b1v.z,b1v.w,
                        b2v.x,b2v.y,b2v.z,b2v.w, b3v.x,b3v.y,b3v.z,b3v.w};
#pragma unroll
        for (int o = 0; o < 16; o++) { sc0[o] = t0[o]; sh0[o] = t1[o]; }
    }

    float s[8], q[8];
#pragma unroll
    for (int o = 0; o < 8; o++) { s[o] = 0.0f; q[o] = 0.0f; }

    for (int pos = blockIdx.x * 256 + threadIdx.x; pos < NPOS; pos += gridDim.x * 256) {
        const float4* pv = (const float4*)(g_v + (size_t)pos * 8);
        float4 v0 = pv[0], v1 = pv[1];
        float v[8] = {v0.x, v0.y, v0.z, v0.w, v1.x, v1.y, v1.z, v1.w};
        float z[16];
#pragma unroll
        for (int o = 0; o < 16; o++) {
            float y = 0.0f;
#pragma unroll
            for (int i = 0; i < 8; i++) y = fmaf(c_w0[o * 8 + i], v[i], y);
            z[o] = fmaxf(fmaf(y, sc0[o], sh0[o]), 0.0f);
        }
#pragma unroll
        for (int o = 0; o < 8; o++) {
            float y = 0.0f;
#pragma unroll
            for (int i = 0; i < 16; i++) y = fmaf(c_w1[o * 16 + i], z[i], y);
            s[o] += y;
            q[o]  = fmaf(y, y, q[o]);
        }
    }
#pragma unroll
    for (int o = 0; o < 8; o++) { block_acc(s[o], &red[o]); block_acc(q[o], &red[8 + o]); }
    __syncthreads();
    if (threadIdx.x < 16) atomicAdd(&g_st1[threadIdx.x], (double)red[threadIdx.x]);
}

// ---------------- K5: fold BN1 --------------------------------------------------
__global__ void k_fin1(const float* __restrict__ g1, const float* __restrict__ b1) {
    int o = threadIdx.x;
    if (o >= 8) return;
    const double N = (double)NPOS;
    double m    = g_st1[o] / N;
    double var  = g_st1[8 + o] / N - m * m;
    double rstd = rsqrt(var + EPSq);
    double gg   = (double)g1[o];
    g_sc1[o] = (float)(gg * rstd);
    g_sh1[o] = (float)((double)b1[o] - m * rstd * gg);
}

// ---------------- K6: final MLP + sigmoid ---------------------------------------
__global__ void __launch_bounds__(256) k_final(float* __restrict__ out) {
    int pos = blockIdx.x * 256 + threadIdx.x;   // grid sized exactly

    float sc0[16], sh0[16], sc1[8], sh1[8];
    {
        const float4* p = (const float4*)g_sc0;
        float4 a0 = p[0], a1 = p[1], a2 = p[2], a3 = p[3];
        float t0[16] = {a0.x,a0.y,a0.z,a0.w, a1.x,a1.y,a1.z,a1.w,
                        a2.x,a2.y,a2.z,a2.w, a3.x,a3.y,a3.z,a3.w};
        const float4* q = (const float4*)g_sh0;
        float4 b0v = q[0], b1v = q[1], b2v = q[2], b3v = q[3];
        float t1[16] = {b0v.x,b0v.y,b0v.z,b0v.w, b1v.x,b1v.y,b1v.z,b1v.w,
                        b2v.x,b2v.y,b2v.z,b2v.w, b3v.x,b3v.y,b3v.z,b3v.w};
#pragma unroll
        for (int o = 0; o < 16; o++) { sc0[o] = t0[o]; sh0[o] = t1[o]; }
        const float4* r = (const float4*)g_sc1;
        float4 c0 = r[0], c1 = r[1];
        const float4* u = (const float4*)g_sh1;
        float4 d0 = u[0], d1 = u[1];
        float t2[8] = {c0.x,c0.y,c0.z,c0.w, c1.x,c1.y,c1.z,c1.w};
        float t3[8] = {d0.x,d0.y,d0.z,d0.w, d1.x,d1.y,d1.z,d1.w};
#pragma unroll
        for (int o = 0; o < 8; o++) { sc1[o] = t2[o]; sh1[o] = t3[o]; }
    }

    const float4* pv = (const float4*)(g_v + (size_t)pos * 8);
    float4 v0 = pv[0], v1 = pv[1];
    float v[8] = {v0.x, v0.y, v0.z, v0.w, v1.x, v1.y, v1.z, v1.w};

    float z[16];
#pragma unroll
    for (int o = 0; o < 16; o++) {
        float y = 0.0f;
#pragma unroll
        for (int i = 0; i < 8; i++) y = fmaf(c_w0[o * 8 + i], v[i], y);
        z[o] = fmaxf(fmaf(y, sc0[o], sh0[o]), 0.0f);
    }
    float z1[8];
#pragma unroll
    for (int o = 0; o < 8; o++) {
        float y = 0.0f;
#pragma unroll
        for (int i = 0; i < 16; i++) y = fmaf(c_w1[o * 16 + i], z[i], y);
        z1[o] = fmaxf(fmaf(y, sc1[o], sh1[o]), 0.0f);
    }
    float acc = c_bs[0];
#pragma unroll
    for (int i = 0; i < 8; i++) acc = fmaf(c_ws[i], z1[i], acc);

    out[pos] = 1.0f / (1.0f + expf(-acc));
}

// ---------------- launch --------------------------------------------------------
extern "C" void kernel_launch(void* const* d_in, const int* in_sizes, int n_in,
                              void* d_out, int out_size) {
    const float* ref  = (const float*)d_in[0];
    const float* grid = (const float*)d_in[1];
    const float* w0   = (const float*)d_in[2];
    const float* g0   = (const float*)d_in[3];
    const float* b0   = (const float*)d_in[4];
    const float* w1   = (const float*)d_in[5];
    const float* g1   = (const float*)d_in[6];
    const float* b1   = (const float*)d_in[7];
    const float* ws   = (const float*)d_in[8];
    const float* bs   = (const float*)d_in[9];
    float* out = (float*)d_out;

    // weights -> constant memory (D2D memcpy nodes, graph-capturable)
    cudaMemcpyToSymbolAsync(c_w0, w0, 128 * sizeof(float), 0, cudaMemcpyDeviceToDevice, 0);
    cudaMemcpyToSymbolAsync(c_w1, w1, 128 * sizeof(float), 0, cudaMemcpyDeviceToDevice, 0);
    cudaMemcpyToSymbolAsync(c_ws, ws,   8 * sizeof(float), 0, cudaMemcpyDeviceToDevice, 0);
    cudaMemcpyToSymbolAsync(c_bs, bs,       sizeof(float), 0, cudaMemcpyDeviceToDevice, 0);

    k_zero<<<1, 128>>>();
    k_transpose<<<dim3(Wq / 32, 1, Bq * Hq), dim3(32, 16)>>>(ref);
    k_gather<<<(NCELL * 8) / 256, 256>>>(grid);          // 5120 blocks, exact
    k_fin0<<<1, 16>>>(g0, b0);
    k_stats1<<<1184, 256>>>();
    k_fin1<<<1, 8>>>(g1, b1);
    k_final<<<NPOS / 256, 256>>>(out);                   // 5760 blocks, exact
}